// round 13
// baseline (speedup 1.0000x reference)
#include <cuda_runtime.h>

#define N_  64
#define T_  4096
#define D_  128
#define GL  1024     // live-kernel blocks
#define GD  512      // dead-kernel blocks
#define BIASL 320    // live table bias: guarantees >=1 live block per n
#define BIASD 768    // dead table bias: guarantees >=1 dead block per n

// Scratch (no allocations allowed anywhere)
__device__ float g_plive [(size_t)GL * D_];      // per live block: [b][D]
__device__ float g_pdead [(size_t)GD * D_];      // per dead block: [b][D]
__device__ float g_wslive[GL];                   // per live block weight sum
__device__ int   g_ticket[N_];                   // zero-init; finisher resets
__device__ int4  g_btabL[GL];                    // (n, lc, cnt, len)
__device__ int4  g_btabD[GD];                    // (n, lc, cnt, len)
__device__ int   g_rngL[N_ * 2];                 // live block range [lo,hi) per n
__device__ int   g_rngD[N_ * 2];                 // dead block range [lo,hi) per n

// ---------------------------------------------------------------------------
// Setup: cost-proportional block allocation for both phase kernels.
//   live weight  = len[n] + BIASL   (bias => every n gets >= 1 live block:
//                                    BIASL*GL > max possible total cost)
//   dead weight  = (T - len[n]) + BIASD  (same guarantee for dead blocks;
//                                         the finisher lives there)
// R12 BUG FIXED: without the live bias, rows with 0 < len < C/GL got ZERO
// live blocks -> their live region was computed by nobody (wrong context,
// poisoned mask).
// Deterministic, 1 block, 64 threads, ~1us.
// ---------------------------------------------------------------------------
__global__ void setup_kernel(const int* __restrict__ slen)
{
    __shared__ int sLen[N_];
    __shared__ int kL[N_ + 1], kD[N_ + 1];
    const int tid = threadIdx.x;
    if (tid < N_) sLen[tid] = slen[tid];
    __syncthreads();
    if (tid == 0) {
        long long CL = 0, CD = 0;
        for (int m = 0; m < N_; m++) {
            CL += sLen[m] + BIASL;
            CD += (T_ - sLen[m]) + BIASD;
        }
        long long pL = 0, pD = 0;
        kL[0] = 0; kD[0] = 0;
        for (int m = 0; m < N_; m++) {
            pL += sLen[m] + BIASL;
            pD += (T_ - sLen[m]) + BIASD;
            kL[m + 1] = (int)((pL * GL) / CL);
            kD[m + 1] = (int)((pD * GD) / CD);
        }
    }
    __syncthreads();
    if (tid < N_) {
        const int len = sLen[tid];
        const int lo = kL[tid], hi = kL[tid + 1];     // hi > lo guaranteed
        g_rngL[tid * 2] = lo;  g_rngL[tid * 2 + 1] = hi;
        for (int b = lo; b < hi; b++)
            g_btabL[b] = make_int4(tid, b - lo, hi - lo, len);
        const int lo2 = kD[tid], hi2 = kD[tid + 1];   // hi2 > lo2 guaranteed
        g_rngD[tid * 2] = lo2;  g_rngD[tid * 2 + 1] = hi2;
        for (int b = lo2; b < hi2; b++)
            g_btabD[b] = make_int4(tid, b - lo2, hi2 - lo2, len);
    }
}

// ---------------------------------------------------------------------------
// LIVE kernel: contiguous windows of [0, len[n]). R8-proven loop shape:
// warp owns a CONTIGUOUS t-run, batch-4 front loads (8x LDG.128 in flight),
// w = exp(<key,q>), acc += w*value, ws += w. Writes mask=1 for its window.
// (No max-sub: |dot| << 88 fp32 exp range; softmax cancels shifts exactly.)
// ---------------------------------------------------------------------------
__global__ void __launch_bounds__(256, 8) live_kernel(
    const float* __restrict__ q,
    const float* __restrict__ key,
    const float* __restrict__ value,
    float* __restrict__ mask_out)
{
    const int4 tab = g_btabL[blockIdx.x];
    const int  n = tab.x, lc = tab.y, cnt = tab.z, len = tab.w;
    const int lane = threadIdx.x & 31;
    const int wp   = threadIdx.x >> 5;

    const int t0 = (int)(((long long)len * lc) / cnt);
    const int t1 = (int)(((long long)len * (lc + 1)) / cnt);

    for (int t = t0 + threadIdx.x; t < t1; t += 256)
        mask_out[(size_t)n * T_ + t] = 1.0f;

    const float4 qv = reinterpret_cast<const float4*>(q + (size_t)n * D_)[lane];
    const float4* __restrict__ k4 = reinterpret_cast<const float4*>(key);
    const float4* __restrict__ v4 = reinterpret_cast<const float4*>(value);
    const size_t strideT = (size_t)N_ * (D_ / 4);

    // contiguous per-warp run [a, b)
    const int M = t1 - t0;
    const int a = t0 + (int)(((long long)M * wp) >> 3);
    const int b = t0 + (int)(((long long)M * (wp + 1)) >> 3);

    float4 acc = make_float4(0.f, 0.f, 0.f, 0.f);
    float  ws  = 0.0f;

    size_t o = ((size_t)a * N_ + n) * (D_ / 4) + lane;
    int t = a;
    for (; t + 4 <= b; t += 4) {
        float4 kv[4], vv[4];
#pragma unroll
        for (int u = 0; u < 4; u++) {
            kv[u] = k4[o + (size_t)u * strideT];
            vv[u] = v4[o + (size_t)u * strideT];
        }
#pragma unroll
        for (int u = 0; u < 4; u++) {
            float p = kv[u].x*qv.x + kv[u].y*qv.y + kv[u].z*qv.z + kv[u].w*qv.w;
            p += __shfl_xor_sync(0xffffffffu, p, 16);
            p += __shfl_xor_sync(0xffffffffu, p, 8);
            p += __shfl_xor_sync(0xffffffffu, p, 4);
            p += __shfl_xor_sync(0xffffffffu, p, 2);
            p += __shfl_xor_sync(0xffffffffu, p, 1);
            const float w = __expf(p);
            ws += w;
            acc.x += w*vv[u].x;  acc.y += w*vv[u].y;
            acc.z += w*vv[u].z;  acc.w += w*vv[u].w;
        }
        o += 4 * strideT;
    }
    for (; t < b; t++) {
        const float4 kv = k4[o];
        const float4 vv = v4[o];
        float p = kv.x*qv.x + kv.y*qv.y + kv.z*qv.z + kv.w*qv.w;
        p += __shfl_xor_sync(0xffffffffu, p, 16);
        p += __shfl_xor_sync(0xffffffffu, p, 8);
        p += __shfl_xor_sync(0xffffffffu, p, 4);
        p += __shfl_xor_sync(0xffffffffu, p, 2);
        p += __shfl_xor_sync(0xffffffffu, p, 1);
        const float w = __expf(p);
        ws += w;
        acc.x += w*vv.x;  acc.y += w*vv.y;  acc.z += w*vv.z;  acc.w += w*vv.w;
        o += strideT;
    }

    __shared__ float4 red[8][32];
    __shared__ float  wsum[8];
    red[wp][lane] = acc;
    if (lane == 0) wsum[wp] = ws;
    __syncthreads();
    if (wp == 0) {
        float4 s = red[0][lane];
#pragma unroll
        for (int k = 1; k < 8; k++) {
            const float4 r = red[k][lane];
            s.x += r.x;  s.y += r.y;  s.z += r.z;  s.w += r.w;
        }
        reinterpret_cast<float4*>(g_plive + (size_t)blockIdx.x * D_)[lane] = s;
        if (lane == 0) {
            float tt = 0.0f;
#pragma unroll
            for (int k = 0; k < 8; k++) tt += wsum[k];
            g_wslive[blockIdx.x] = tt;
        }
    }
}

// ---------------------------------------------------------------------------
// DEAD kernel: contiguous windows of [len[n], T). w = exp(0) = 1 -> key rows
// never loaded (the ~25% traffic cut). Pure value streaming, batch-4.
// Writes mask=0. Last dead block per n (ticket) does the final reduce over
// this n's live blocks (complete: kernel ordering) + dead blocks, in fixed
// index order -> deterministic. Dead weight sum is analytic: T - len.
// ---------------------------------------------------------------------------
__global__ void __launch_bounds__(256, 8) dead_kernel(
    const float* __restrict__ value,
    float* __restrict__ out_ctx,
    float* __restrict__ mask_out)
{
    const int4 tab = g_btabD[blockIdx.x];
    const int  n = tab.x, lc = tab.y, cnt = tab.z, len = tab.w;
    const int lane = threadIdx.x & 31;
    const int wp   = threadIdx.x >> 5;

    const int span = T_ - len;
    const int t0 = len + (int)(((long long)span * lc) / cnt);
    const int t1 = len + (int)(((long long)span * (lc + 1)) / cnt);

    for (int t = t0 + threadIdx.x; t < t1; t += 256)
        mask_out[(size_t)n * T_ + t] = 0.0f;

    const float4* __restrict__ v4 = reinterpret_cast<const float4*>(value);
    const size_t strideT = (size_t)N_ * (D_ / 4);

    const int M = t1 - t0;
    const int a = t0 + (int)(((long long)M * wp) >> 3);
    const int b = t0 + (int)(((long long)M * (wp + 1)) >> 3);

    float4 acc = make_float4(0.f, 0.f, 0.f, 0.f);
    size_t o = ((size_t)a * N_ + n) * (D_ / 4) + lane;
    int t = a;
    for (; t + 4 <= b; t += 4) {
        float4 vv[4];
#pragma unroll
        for (int u = 0; u < 4; u++) vv[u] = v4[o + (size_t)u * strideT];
#pragma unroll
        for (int u = 0; u < 4; u++) {
            acc.x += vv[u].x;  acc.y += vv[u].y;
            acc.z += vv[u].z;  acc.w += vv[u].w;
        }
        o += 4 * strideT;
    }
    for (; t < b; t++) {
        const float4 vv = v4[o];
        acc.x += vv.x;  acc.y += vv.y;  acc.z += vv.z;  acc.w += vv.w;
        o += strideT;
    }

    __shared__ float4 red[8][32];
    __shared__ int    isLast;
    red[wp][lane] = acc;
    __syncthreads();
    if (wp == 0) {
        float4 s = red[0][lane];
#pragma unroll
        for (int k = 1; k < 8; k++) {
            const float4 r = red[k][lane];
            s.x += r.x;  s.y += r.y;  s.z += r.z;  s.w += r.w;
        }
        reinterpret_cast<float4*>(g_pdead + (size_t)blockIdx.x * D_)[lane] = s;
        __threadfence();
    }
    __syncthreads();

    if (threadIdx.x == 0)
        isLast = (atomicAdd(&g_ticket[n], 1) == cnt - 1) ? 1 : 0;
    __syncthreads();

    if (isLast) {
        const int llo = g_rngL[n * 2], lhi = g_rngL[n * 2 + 1];
        const int dlo = g_rngD[n * 2], dhi = g_rngD[n * 2 + 1];
        if (threadIdx.x < D_) {
            const int d = threadIdx.x;
            float rs = (float)(T_ - len);            // dead weights: exp(0)=1 each
            for (int k = llo; k < lhi; k++)
                rs += __ldcg(&g_wslive[k]);
            float s = 0.0f;
            for (int k = llo; k < lhi; k++)
                s += __ldcg(&g_plive[(size_t)k * D_ + d]);
            for (int k = dlo; k < dhi; k++)
                s += __ldcg(&g_pdead[(size_t)k * D_ + d]);
            out_ctx[(size_t)n * D_ + d] = s / rs;
        }
        if (threadIdx.x == 0) g_ticket[n] = 0;       // reset for next replay
    }
}

// ---------------------------------------------------------------------------
extern "C" void kernel_launch(void* const* d_in, const int* in_sizes, int n_in,
                              void* d_out, int out_size)
{
    const float* query = (const float*)d_in[0];
    const float* key   = (const float*)d_in[1];
    const float* value = (const float*)d_in[2];
    const int*   slen  = (const int*)d_in[3];   // int32 on device (JAX x64 off)

    float* out_ctx  = (float*)d_out;           // (N, D)
    float* out_mask = (float*)d_out + N_ * D_; // (N, T)

    setup_kernel<<<1, 64>>>(slen);
    live_kernel<<<GL, 256>>>(query, key, value, out_mask);
    dead_kernel<<<GD, 256>>>(value, out_ctx, out_mask);
}

// round 14
// speedup vs baseline: 1.5199x; 1.5199x over previous
#include <cuda_runtime.h>

#define N_  64
#define T_  4096
#define D_  128
#define CH  16
#define TCH (T_/CH)   // 256 timesteps per chunk; 32 per warp

// Scratch (no allocations allowed anywhere)
__device__ float g_partial[N_ * CH * D_];    // 512 KB
__device__ float g_chunksum[N_ * CH];        // 4 KB
__device__ int   g_ticket[N_];               // zero-init; finisher resets -> graph-replay safe

// ---------------------------------------------------------------------------
// Fused kernel (R4/R8 configuration -- proven optimum over 10 rounds):
// block (n, c) over t in [c*TCH, (c+1)*TCH):
//   w = exp( (t<len[n]) * <key[t,n,:], q[n,:]> )   (no max-sub needed:
//   |dot| << 88 fp32 exp range; softmax cancels shifts exactly)
//   acc[d] += w * value[t,n,d] ;  ws += w
// Batch-4 front loads (8x LDG.128 in flight), contiguous per-warp t-runs,
// 32 regs -> 8 CTAs/SM (launch_bounds(256,8) pins the budget).
// Alternatives tested and rejected: deep SW pipeline (R5: occ collapse),
// shfl-ILP (R6: reg growth), batch-2 (R7: MLP loss), masked-key skip in all
// forms (R9-R13: balance/overhead/locality penalties exceed the 25% traffic
// cut every time).
// Last block per n reduces the 16 partials and normalizes. Deterministic:
// every sum is taken in fixed index order regardless of arrival order.
// ---------------------------------------------------------------------------
__global__ void __launch_bounds__(256, 8) fused_attn_kernel(
    const float* __restrict__ q,
    const float* __restrict__ key,
    const float* __restrict__ value,
    const int* __restrict__ slen,          // int32 on device (JAX x64 off)
    float* __restrict__ out_ctx,
    float* __restrict__ mask_out)
{
    const int n    = blockIdx.x;           // fast index -> concurrent blocks
    const int c    = blockIdx.y;           //   span all n for one t-window
    const int lane = threadIdx.x & 31;
    const int wp   = threadIdx.x >> 5;
    const int len  = slen[n];

    // Coalesced mask write: 1KB per block
    {
        const int t = c * TCH + threadIdx.x;
        mask_out[(size_t)n * T_ + t] = (t < len) ? 1.0f : 0.0f;
    }

    const float4 qv = reinterpret_cast<const float4*>(q + (size_t)n * D_)[lane];
    const float4* __restrict__ k4 = reinterpret_cast<const float4*>(key);
    const float4* __restrict__ v4 = reinterpret_cast<const float4*>(value);

    const size_t strideT = (size_t)N_ * (D_ / 4);            // per-t stride (float4)
    const int    tbase   = c * TCH + wp * 32;                // this warp's first t
    const size_t idx0    = ((size_t)tbase * N_ + n) * (D_ / 4) + lane;

    float4 acc = make_float4(0.f, 0.f, 0.f, 0.f);
    float  ws  = 0.0f;

#pragma unroll
    for (int i = 0; i < 32; i += 4) {
        float4 kv[4], vv[4];
#pragma unroll
        for (int j = 0; j < 4; j++) {
            const size_t o = idx0 + (size_t)(i + j) * strideT;
            kv[j] = k4[o];
            vv[j] = v4[o];
        }
#pragma unroll
        for (int j = 0; j < 4; j++) {
            float p = kv[j].x * qv.x + kv[j].y * qv.y
                    + kv[j].z * qv.z + kv[j].w * qv.w;
            p += __shfl_xor_sync(0xffffffffu, p, 16);
            p += __shfl_xor_sync(0xffffffffu, p, 8);
            p += __shfl_xor_sync(0xffffffffu, p, 4);
            p += __shfl_xor_sync(0xffffffffu, p, 2);
            p += __shfl_xor_sync(0xffffffffu, p, 1);       // all lanes hold dot
            const float m = (tbase + i + j < len) ? 1.0f : 0.0f;
            const float w = __expf(m * p);                 // multiplicative mask
            ws += w;
            acc.x += w * vv[j].x;  acc.y += w * vv[j].y;
            acc.z += w * vv[j].z;  acc.w += w * vv[j].w;
        }
    }

    // Cross-warp reduce (fixed order -> deterministic)
    __shared__ float4 red[8][32];
    __shared__ float  wsum[8];
    __shared__ int    isLast;
    red[wp][lane] = acc;
    if (lane == 0) wsum[wp] = ws;
    __syncthreads();

    if (wp == 0) {
        float4 s = red[0][lane];
#pragma unroll
        for (int k = 1; k < 8; k++) {
            const float4 r = red[k][lane];
            s.x += r.x;  s.y += r.y;  s.z += r.z;  s.w += r.w;
        }
        reinterpret_cast<float4*>(g_partial + ((size_t)n * CH + c) * D_)[lane] = s;
        if (lane == 0) {
            float t = 0.0f;
#pragma unroll
            for (int k = 0; k < 8; k++) t += wsum[k];
            g_chunksum[n * CH + c] = t;
        }
        __threadfence();   // make this warp's partial/chunksum globally visible
    }
    __syncthreads();

    // Completion ticket: last block for this n does the final reduce.
    if (threadIdx.x == 0)
        isLast = (atomicAdd(&g_ticket[n], 1) == CH - 1) ? 1 : 0;
    __syncthreads();

    if (isLast) {
        if (threadIdx.x < D_) {
            const int d = threadIdx.x;
            float rs = 0.0f;
#pragma unroll
            for (int k = 0; k < CH; k++)
                rs += __ldcg(&g_chunksum[n * CH + k]);      // L1-bypass: other CTAs' data
            float s = 0.0f;
#pragma unroll
            for (int k = 0; k < CH; k++)
                s += __ldcg(&g_partial[((size_t)n * CH + k) * D_ + d]);
            out_ctx[(size_t)n * D_ + d] = s / rs;
        }
        if (threadIdx.x == 0) g_ticket[n] = 0;   // reset for next replay
    }
}

// ---------------------------------------------------------------------------
extern "C" void kernel_launch(void* const* d_in, const int* in_sizes, int n_in,
                              void* d_out, int out_size)
{
    const float* query = (const float*)d_in[0];
    const float* key   = (const float*)d_in[1];
    const float* value = (const float*)d_in[2];
    const int*   slen  = (const int*)d_in[3];   // int32 on device (JAX x64 off)

    float* out_ctx  = (float*)d_out;           // (N, D)
    float* out_mask = (float*)d_out + N_ * D_; // (N, T)

    dim3 g(N_, CH);   // n fastest -> concurrent CTAs read contiguous windows
    fused_attn_kernel<<<g, 256>>>(query, key, value, slen, out_ctx, out_mask);
}